// round 10
// baseline (speedup 1.0000x reference)
#include <cuda_runtime.h>
#include <math.h>

#define NROWS 1024
#define C 64
#define MARGIN_F 15.0f
#define EPSJ 1e-8f
#define HLN2 0.34657359027997264f   /* 0.5*ln2 */

/* gram kernel tiling */
#define GTI 32
#define GTJ 64
/* js kernel tiling */
#define JTI 32
#define JTJ 32
#define NBLKJ 1024                   /* total js blocks across both launches */

typedef unsigned long long ull;

// ---------------- scratch (static device globals; no allocation) ----------------
__device__ float g_K[2][NROWS];      // 0.5*Sa + 0.5*ln2*sumA  per row
__device__ float g_nn[2][NROWS];     // ||x||^2 per row
__device__ float g_pos[2 * NROWS];   // per-row positive-branch contribution
__device__ float g_oodv[2 * NROWS];  // per-row ood contribution (var*coffi)
__device__ float g_rowsum[NROWS];    // negative-branch per-row pair sums
__device__ int   g_rowcnt[NROWS];    // negative-branch per-row counts
__device__ int   g_done;             // js-kernel completion counter
__device__ float g_w[NROWS][NROWS];  // per-pair weight hinge*(1-dl)  (4 MB)

__device__ __forceinline__ ull fma2(ull a, ull b, ull c) {
    ull d;
    asm("fma.rn.f32x2 %0, %1, %2, %3;" : "=l"(d) : "l"(a), "l"(b), "l"(c));
    return d;
}
__device__ __forceinline__ ull add2(ull a, ull b) {
    ull d;
    asm("add.rn.f32x2 %0, %1, %2;" : "=l"(d) : "l"(a), "l"(b));
    return d;
}
__device__ __forceinline__ ull pk(unsigned lo, unsigned hi) {
    return ((ull)hi << 32) | lo;
}
__device__ __forceinline__ ull spl(float v) {
    unsigned b = __float_as_uint(v);
    return pk(b, b);
}

union F4U {
    float4 f;
    ull u[2];
    float s[4];
    unsigned q[4];
};
union U2F {
    ull u;
    float s[2];
    unsigned q[2];
};

__device__ __forceinline__ float wsum(float v) {
    #pragma unroll
    for (int off = 16; off; off >>= 1) v += __shfl_xor_sync(0xffffffffu, v, off);
    return v;
}
__device__ __forceinline__ float wmin(float v) {
    #pragma unroll
    for (int off = 16; off; off >>= 1)
        v = fminf(v, __shfl_xor_sync(0xffffffffu, v, off));
    return v;
}

// ---------------- kernel 1: warp-per-row precompute + positive + ood ------------
__global__ void row_kernel(const float* __restrict__ x1, const float* __restrict__ x2,
                           const float* __restrict__ xp1, const float* __restrict__ xp2,
                           const float* __restrict__ l1,  const float* __restrict__ l2) {
    int gtid = blockIdx.x * blockDim.x + threadIdx.x;
    int w    = gtid >> 5;            // warp id: 0..2047
    int lane = gtid & 31;
    if (gtid == 0) g_done = 0;
    if (gtid < NROWS) { g_rowsum[gtid] = 0.0f; g_rowcnt[gtid] = 0; }

    int br = w >> 10;
    int i  = w & (NROWS - 1);
    const float* xr = (br ? x2  : x1)  + i * C;
    const float* pr = (br ? xp2 : xp1) + i * C;
    const float* lr = (br ? l2  : l1)  + i * C;

    float xv0 = xr[lane], xv1 = xr[lane + 32];
    float A0  = pr[lane] + EPSJ, A1 = pr[lane + 32] + EPSJ;
    float lv0 = lr[lane], lv1 = lr[lane + 32];

    float nn = wsum(fmaf(xv0, xv0, xv1 * xv1));

    float la0 = __logf(A0),                 la1 = __logf(A1);
    float L00 = __logf(0.5f * (A0 + EPSJ)), L01 = __logf(0.5f * (A1 + EPSJ));
    float L10 = __logf(0.5f * (A0 + 1.0f)), L11 = __logf(0.5f * (A1 + 1.0f));
    float P  = fmaf(A0, la0 - L00, A1 * (la1 - L01));
    float T  = L00 + L01;
    float Sa = fmaf(A0, la0, A1 * la1);
    float sA = A0 + A1;

    float pd0 = sqrtf(fmaxf(nn - 2.0f * xv0 + 1.0f, 1e-12f));
    float pd1 = sqrtf(fmaxf(nn - 2.0f * xv1 + 1.0f, 1e-12f));
    float h0  = -0.5f * A0 * (L00 - L10) - 0.5f * EPSJ * L00 + 0.5f * L10;
    float h1  = -0.5f * A1 * (L01 - L11) - 0.5f * EPSJ * L01 + 0.5f * L11;
    float w0  = pd0 * lv0, w1 = pd1 * lv1;
    float S1  = w0 + w1;
    float S2  = fmaf(w0, h0, w1 * h1);
    float r0  = fmaxf(MARGIN_F - pd0, 0.0f) * (1.0f / MARGIN_F);
    float r1  = fmaxf(MARGIN_F - pd1, 0.0f) * (1.0f / MARGIN_F);
    float var = fmaf(r0, r0, r1 * r1);
    float mn  = fminf(1.0f - r0, 1.0f - r1);

    P = wsum(P); T = wsum(T); Sa = wsum(Sa); sA = wsum(sA);
    S1 = wsum(S1); S2 = wsum(S2); var = wsum(var); mn = wmin(mn);

    if (lane == 0) {
        const float LOGEPS = -18.420680743952367f;   // ln(1e-8)
        float G = 1.0f - 0.5f * P - 0.5f * EPSJ * (float)(C - 1) * LOGEPS
                       + 0.5f * EPSJ * T;
        g_pos [w]   = G * S1 + S2;
        g_oodv[w]   = var * mn;
        g_K [br][i] = 0.5f * Sa + HLN2 * sA;
        g_nn[br][i] = nn;
    }
}

// ---------------- kernel 2: gram + weights --------------------------------------
__global__ void __launch_bounds__(128, 4)
gram_kernel(const float* __restrict__ x1, const float* __restrict__ x2,
            const float* __restrict__ l1,  const float* __restrict__ l2) {
    extern __shared__ float sm[];
    float2* sPi = (float2*)sm;            // [C][GTI] (l1,x1)  16 KB
    float2* sPj = sPi + C * GTI;          // [C][GTJ] (l2,x2)  32 KB

    const int tx = threadIdx.x, ty = threadIdx.y;
    const int tid = ty * 16 + tx;
    const int i0 = blockIdx.y * GTI, j0 = blockIdx.x * GTJ;

    {
        int r = tid & 31, c0 = tid >> 5;          // c0: 0..3
        #pragma unroll
        for (int p = 0; p < 4; p++) {
            int cb = c0 + 4 * p;
            float4 lv = *(const float4*)&l1[(i0 + r) * C + cb * 4];
            float4 xv = *(const float4*)&x1[(i0 + r) * C + cb * 4];
            sPi[(cb * 4 + 0) * GTI + r] = make_float2(lv.x, xv.x);
            sPi[(cb * 4 + 1) * GTI + r] = make_float2(lv.y, xv.y);
            sPi[(cb * 4 + 2) * GTI + r] = make_float2(lv.z, xv.z);
            sPi[(cb * 4 + 3) * GTI + r] = make_float2(lv.w, xv.w);
        }
    }
    {
        int r = tid & 63, c0 = tid >> 6;          // c0: 0..1
        #pragma unroll
        for (int p = 0; p < 8; p++) {
            int cb = c0 + 2 * p;
            float4 lv = *(const float4*)&l2[(j0 + r) * C + cb * 4];
            float4 xv = *(const float4*)&x2[(j0 + r) * C + cb * 4];
            sPj[(cb * 4 + 0) * GTJ + r] = make_float2(lv.x, xv.x);
            sPj[(cb * 4 + 1) * GTJ + r] = make_float2(lv.y, xv.y);
            sPj[(cb * 4 + 2) * GTJ + r] = make_float2(lv.z, xv.z);
            sPj[(cb * 4 + 3) * GTJ + r] = make_float2(lv.w, xv.w);
        }
    }
    __syncthreads();

    ull dlx[4][4];
    #pragma unroll
    for (int a = 0; a < 4; a++)
        #pragma unroll
        for (int b = 0; b < 4; b++) dlx[a][b] = 0ull;

    const float4* pi4 = (const float4*)sPi + ty * 2;
    const float4* pj4 = (const float4*)sPj + tx * 2;

    #pragma unroll 4
    for (int c = 0; c < C; c++) {
        F4U pia, pib, pja, pjb;
        pia.f = pi4[c * (GTI / 2)];
        pib.f = pi4[c * (GTI / 2) + 1];
        pja.f = pj4[c * (GTJ / 2)];
        pjb.f = pj4[c * (GTJ / 2) + 1];
        ull pi[4] = {pia.u[0], pia.u[1], pib.u[0], pib.u[1]};
        ull pj[4] = {pja.u[0], pja.u[1], pjb.u[0], pjb.u[1]};
        #pragma unroll
        for (int ki = 0; ki < 4; ki++)
            #pragma unroll
            for (int kj = 0; kj < 4; kj++)
                dlx[ki][kj] = fma2(pi[ki], pj[kj], dlx[ki][kj]);
    }

    F4U nb, na;
    nb.f = *(const float4*)&g_nn[1][j0 + tx * 4];
    na.f = *(const float4*)&g_nn[0][i0 + ty * 4];

    #pragma unroll
    for (int ki = 0; ki < 4; ki++) {
        int i = i0 + ty * 4 + ki;
        F4U wv;
        int rcnt = 0;
        #pragma unroll
        for (int kj = 0; kj < 4; kj++) {
            float2 v = *(float2*)&dlx[ki][kj];           // (dl, dx)
            float d2 = fmaxf(na.s[ki] + nb.s[kj] - 2.0f * v.y, 1e-12f);
            float ed = sqrtf(d2) + 1e-10f;
            float hinge = fmaxf(MARGIN_F - ed, 0.0f);
            float w = hinge * (1.0f - v.x);
            wv.s[kj] = w;
            rcnt += (w > 0.0f) ? 1 : 0;
        }
        *(float4*)&g_w[i][j0 + tx * 4] = wv.f;
        #pragma unroll
        for (int off = 8; off; off >>= 1)
            rcnt += __shfl_down_sync(0xffffffffu, rcnt, off, 16);
        if (tx == 0) atomicAdd(&g_rowcnt[i], rcnt);
    }
}

// ---------------- kernel 3: js log-sums, hybrid MUFU + f32x2 polynomial ---------
// 32i x 32j tile, 128 thr (8tx x 16ty), 2i x 4j micro-tile.
// Per c-iter per (ki): kj0,kj1 via packed-f32x2 polynomial log2 on the FMA pipe,
// kj2,kj3 via MUFU.LG2 -> both pipes saturate concurrently, halving the
// per-c-iter cost vs pure MUFU (rt_LG2 ~ 16).
// Poly: s in [2e-8,2): f = mantissa in [1,2) (one LOP3); E = (ix>>23)-127 exact
// via bias trick (no I2F); lg2(s) = E + B(f-1.5), B = deg-7 Taylor of log2
// about 1.5 (max err 3.7e-5, ~2000x inside rel-err budget).
__global__ void __launch_bounds__(128, 8)
js_kernel(const float* __restrict__ xp1, const float* __restrict__ xp2,
          int jbase, float* __restrict__ out, int out_size) {
    __shared__ ull  sA2[C * JTI];            // (a,a) duplicated   16 KB
    __shared__ float sB [C * JTJ];           // b                   8 KB

    const int tx = threadIdx.x, ty = threadIdx.y;   // tx 0..7, ty 0..15
    const int tid = ty * 8 + tx;
    const int i0 = blockIdx.y * JTI, j0 = jbase + blockIdx.x * JTJ;

    {
        int r = tid & 31, c0 = tid >> 5;             // c0: 0..3
        #pragma unroll
        for (int p = 0; p < 4; p++) {
            int cb = c0 + 4 * p;                     // 0..15
            float4 u = *(const float4*)&xp1[(i0 + r) * C + cb * 4];
            float4 v = *(const float4*)&xp2[(j0 + r) * C + cb * 4];
            sA2[(cb * 4 + 0) * JTI + r] = spl(u.x + EPSJ);
            sA2[(cb * 4 + 1) * JTI + r] = spl(u.y + EPSJ);
            sA2[(cb * 4 + 2) * JTI + r] = spl(u.z + EPSJ);
            sA2[(cb * 4 + 3) * JTI + r] = spl(u.w + EPSJ);
            sB [(cb * 4 + 0) * JTJ + r] = v.x + EPSJ;
            sB [(cb * 4 + 1) * JTJ + r] = v.y + EPSJ;
            sB [(cb * 4 + 2) * JTJ + r] = v.z + EPSJ;
            sB [(cb * 4 + 3) * JTJ + r] = v.w + EPSJ;
        }
    }

    // prefetch pair weights / constants
    F4U w0, w1;
    w0.f = __ldg((const float4*)&g_w[i0 + ty * 2 + 0][j0 + tx * 4]);
    w1.f = __ldg((const float4*)&g_w[i0 + ty * 2 + 1][j0 + tx * 4]);
    float2 Ka = __ldg((const float2*)&g_K[0][i0 + ty * 2]);
    F4U Kb; Kb.f = __ldg((const float4*)&g_K[1][j0 + tx * 4]);

    // poly constants (splatted f32x2); Taylor of log2 about f=1.5
    const ull CB0 = spl( 0.5849625007f);
    const ull CB1 = spl( 0.9617966939f);
    const ull CB2 = spl(-0.3205988980f);
    const ull CB3 = spl( 0.1424883991f);
    const ull CB4 = spl(-0.0712441996f);
    const ull CB5 = spl( 0.0379969064f);
    const ull CB6 = spl(-0.0211094300f);
    const ull CB7 = spl( 0.0120624400f);
    const ull CME = spl(-8388735.0f);        // -(2^23 + 127)
    const ull CMH = spl(-1.5f);

    __syncthreads();

    ull   jp[2];                             // packed jsum (kj0,kj1) per ki
    float jm[2][2];                          // scalar jsum (kj2,kj3) per ki
    jp[0] = jp[1] = 0ull;
    jm[0][0] = jm[0][1] = jm[1][0] = jm[1][1] = 0.0f;

    const ull*   aPtr = sA2 + ty * 2;        // stride JTI per c
    const float4* b4  = (const float4*)sB + tx;   // stride JTJ/4=8 per c

    #pragma unroll 4
    for (int c = 0; c < C; c++) {
        ull aa0 = aPtr[c * JTI];
        ull aa1 = aPtr[c * JTI + 1];
        F4U bv; bv.f = b4[c * (JTJ / 4)];

        #pragma unroll
        for (int ki = 0; ki < 2; ki++) {
            ull aa = ki ? aa1 : aa0;
            // --- poly path: kj0,kj1 packed ---
            U2F s2; s2.u = add2(aa, bv.u[0]);
            unsigned fe0 = (s2.q[0] >> 23) + 0x4B000000u;
            unsigned fe1 = (s2.q[1] >> 23) + 0x4B000000u;
            ull E2 = add2(pk(fe0, fe1), CME);         // exact E = exp-127
            unsigned f0 = (s2.q[0] & 0x007FFFFFu) | 0x3F800000u;
            unsigned f1 = (s2.q[1] & 0x007FFFFFu) | 0x3F800000u;
            ull u2 = add2(pk(f0, f1), CMH);           // f - 1.5 in [-0.5, 0.5)
            ull P = CB7;
            P = fma2(P, u2, CB6);
            P = fma2(P, u2, CB5);
            P = fma2(P, u2, CB4);
            P = fma2(P, u2, CB3);
            P = fma2(P, u2, CB2);
            P = fma2(P, u2, CB1);
            P = fma2(P, u2, CB0);                     // B(u) ~ log2(f)
            ull lg2 = add2(P, E2);
            jp[ki] = fma2(s2.u, lg2, jp[ki]);

            // --- MUFU path: kj2,kj3 scalar ---
            U2F av; av.u = aa;
            float a = av.s[0];
            float sa2 = a + bv.s[2];
            float sa3 = a + bv.s[3];
            jm[ki][0] = fmaf(sa2, __log2f(sa2), jm[ki][0]);
            jm[ki][1] = fmaf(sa3, __log2f(sa3), jm[ki][1]);
        }
    }

    #pragma unroll
    for (int ki = 0; ki < 2; ki++) {
        int i = i0 + ty * 2 + ki;
        float Kai = (ki == 0) ? Ka.x : Ka.y;
        const F4U& wv = (ki == 0) ? w0 : w1;
        U2F jpv; jpv.u = jp[ki];
        float js0 = Kai + Kb.s[0] - HLN2 * jpv.s[0];
        float js1 = Kai + Kb.s[1] - HLN2 * jpv.s[1];
        float js2 = Kai + Kb.s[2] - HLN2 * jm[ki][0];
        float js3 = Kai + Kb.s[3] - HLN2 * jm[ki][1];
        float rsum = wv.s[0] * js0 + wv.s[1] * js1 + wv.s[2] * js2 + wv.s[3] * js3;
        #pragma unroll
        for (int off = 4; off; off >>= 1)
            rsum += __shfl_down_sync(0xffffffffu, rsum, off, 8);
        if (tx == 0) atomicAdd(&g_rowsum[i], rsum);
    }

    // ---- folded finalize: last block (across BOTH js launches) reduces ----
    __threadfence();
    __syncthreads();
    __shared__ int s_last;
    if (tid == 0) s_last = atomicAdd(&g_done, 1);
    __syncthreads();
    if (s_last != NBLKJ - 1) return;

    float nega = 0.0f, posi = 0.0f, ood = 0.0f;
    for (int r = tid; r < NROWS; r += 128) {
        float rs = __ldcg(&g_rowsum[r]);
        int   rc = __ldcg(&g_rowcnt[r]);
        nega += rs / (float)(rc > 0 ? rc : 1);
    }
    for (int r = tid; r < 2 * NROWS; r += 128) {
        posi += g_pos[r];
        ood  += g_oodv[r];
    }
    float* red = (float*)sA2;
    red[tid]       = nega;
    red[128 + tid] = posi;
    red[256 + tid] = ood;
    __syncthreads();
    for (int off = 64; off; off >>= 1) {
        if (tid < off) {
            red[tid]       += red[tid + off];
            red[128 + tid] += red[128 + tid + off];
            red[256 + tid] += red[256 + tid + off];
        }
        __syncthreads();
    }
    for (int r = 3 + tid; r < out_size; r += 128) out[r] = 0.0f;  // defensive
    if (tid == 0) {
        float ng = red[0];
        float ps = 0.5f * red[128];
        float od = 0.5f * red[256];
        if (out_size > 0) out[0] = ps + ng + 0.5f * od;   // LAM = 0.5
        if (out_size > 1) out[1] = ps;
        if (out_size > 2) out[2] = ng;
    }
}

// ---------------- launch ---------------------------------------------------------
extern "C" void kernel_launch(void* const* d_in, const int* in_sizes, int n_in,
                              void* d_out, int out_size) {
    const float* x1  = (const float*)d_in[0];
    const float* x2  = (const float*)d_in[1];
    const float* xp1 = (const float*)d_in[2];
    const float* xp2 = (const float*)d_in[3];
    const float* l1  = (const float*)d_in[4];
    const float* l2  = (const float*)d_in[5];
    float* out = (float*)d_out;

    row_kernel<<<256, 256>>>(x1, x2, xp1, xp2, l1, l2);

    const int gsmem = C * (GTI + GTJ) * (int)sizeof(float2);   // 49,152 B
    cudaFuncSetAttribute(gram_kernel, cudaFuncAttributeMaxDynamicSharedMemorySize,
                         gsmem);
    gram_kernel<<<dim3(NROWS / GTJ, NROWS / GTI), dim3(16, 8), gsmem>>>(x1, x2, l1, l2);

    // js split into two half-j launches (diagnostic attribution; g_done spans both)
    dim3 jgrid((NROWS / 2) / JTJ, NROWS / JTI);
    js_kernel<<<jgrid, dim3(8, 16)>>>(xp1, xp2, 0,          out, out_size);
    js_kernel<<<jgrid, dim3(8, 16)>>>(xp1, xp2, NROWS / 2,  out, out_size);
}

// round 11
// speedup vs baseline: 1.1038x; 1.1038x over previous
#include <cuda_runtime.h>
#include <math.h>

#define NROWS 1024
#define C 64
#define MARGIN_F 15.0f
#define EPSJ 1e-8f
#define HLN2 0.34657359027997264f   /* 0.5*ln2 */

/* gram kernel tiling */
#define GTI 32
#define GTJ 64
/* js kernel tiling */
#define JTI 32
#define JTJ 32
#define NBLKJ 1024                   /* (1024/JTI)*(1024/JTJ), single launch */

typedef unsigned long long ull;

// ---------------- scratch (static device globals; no allocation) ----------------
__device__ float g_K[2][NROWS];      // 0.5*Sa + 0.5*ln2*sumA  per row
__device__ float g_nn[2][NROWS];     // ||x||^2 per row
__device__ float g_pos[2 * NROWS];   // per-row positive-branch contribution
__device__ float g_oodv[2 * NROWS];  // per-row ood contribution (var*coffi)
__device__ float g_rowsum[NROWS];    // negative-branch per-row pair sums
__device__ int   g_rowcnt[NROWS];    // negative-branch per-row counts
__device__ int   g_done;             // js-kernel completion counter
__device__ float g_w[NROWS][NROWS];  // per-pair weight hinge*(1-dl)  (4 MB)

__device__ __forceinline__ ull fma2(ull a, ull b, ull c) {
    ull d;
    asm("fma.rn.f32x2 %0, %1, %2, %3;" : "=l"(d) : "l"(a), "l"(b), "l"(c));
    return d;
}
__device__ __forceinline__ ull add2(ull a, ull b) {
    ull d;
    asm("add.rn.f32x2 %0, %1, %2;" : "=l"(d) : "l"(a), "l"(b));
    return d;
}
__device__ __forceinline__ ull pk(unsigned lo, unsigned hi) {
    return ((ull)hi << 32) | lo;
}
__device__ __forceinline__ ull spl(float v) {
    unsigned b = __float_as_uint(v);
    return pk(b, b);
}

union F4U {
    float4 f;
    ull u[2];
    float s[4];
    unsigned q[4];
};
union U2F {
    ull u;
    float s[2];
    unsigned q[2];
};

__device__ __forceinline__ float wsum(float v) {
    #pragma unroll
    for (int off = 16; off; off >>= 1) v += __shfl_xor_sync(0xffffffffu, v, off);
    return v;
}
__device__ __forceinline__ float wmin(float v) {
    #pragma unroll
    for (int off = 16; off; off >>= 1)
        v = fminf(v, __shfl_xor_sync(0xffffffffu, v, off));
    return v;
}

// ---------------- kernel 1: warp-per-row precompute + positive + ood ------------
__global__ void row_kernel(const float* __restrict__ x1, const float* __restrict__ x2,
                           const float* __restrict__ xp1, const float* __restrict__ xp2,
                           const float* __restrict__ l1,  const float* __restrict__ l2) {
    int gtid = blockIdx.x * blockDim.x + threadIdx.x;
    int w    = gtid >> 5;            // warp id: 0..2047
    int lane = gtid & 31;
    if (gtid == 0) g_done = 0;
    if (gtid < NROWS) { g_rowsum[gtid] = 0.0f; g_rowcnt[gtid] = 0; }

    int br = w >> 10;
    int i  = w & (NROWS - 1);
    const float* xr = (br ? x2  : x1)  + i * C;
    const float* pr = (br ? xp2 : xp1) + i * C;
    const float* lr = (br ? l2  : l1)  + i * C;

    float xv0 = xr[lane], xv1 = xr[lane + 32];
    float A0  = pr[lane] + EPSJ, A1 = pr[lane + 32] + EPSJ;
    float lv0 = lr[lane], lv1 = lr[lane + 32];

    float nn = wsum(fmaf(xv0, xv0, xv1 * xv1));

    float la0 = __logf(A0),                 la1 = __logf(A1);
    float L00 = __logf(0.5f * (A0 + EPSJ)), L01 = __logf(0.5f * (A1 + EPSJ));
    float L10 = __logf(0.5f * (A0 + 1.0f)), L11 = __logf(0.5f * (A1 + 1.0f));
    float P  = fmaf(A0, la0 - L00, A1 * (la1 - L01));
    float T  = L00 + L01;
    float Sa = fmaf(A0, la0, A1 * la1);
    float sA = A0 + A1;

    float pd0 = sqrtf(fmaxf(nn - 2.0f * xv0 + 1.0f, 1e-12f));
    float pd1 = sqrtf(fmaxf(nn - 2.0f * xv1 + 1.0f, 1e-12f));
    float h0  = -0.5f * A0 * (L00 - L10) - 0.5f * EPSJ * L00 + 0.5f * L10;
    float h1  = -0.5f * A1 * (L01 - L11) - 0.5f * EPSJ * L01 + 0.5f * L11;
    float w0  = pd0 * lv0, w1 = pd1 * lv1;
    float S1  = w0 + w1;
    float S2  = fmaf(w0, h0, w1 * h1);
    float r0  = fmaxf(MARGIN_F - pd0, 0.0f) * (1.0f / MARGIN_F);
    float r1  = fmaxf(MARGIN_F - pd1, 0.0f) * (1.0f / MARGIN_F);
    float var = fmaf(r0, r0, r1 * r1);
    float mn  = fminf(1.0f - r0, 1.0f - r1);

    P = wsum(P); T = wsum(T); Sa = wsum(Sa); sA = wsum(sA);
    S1 = wsum(S1); S2 = wsum(S2); var = wsum(var); mn = wmin(mn);

    if (lane == 0) {
        const float LOGEPS = -18.420680743952367f;   // ln(1e-8)
        float G = 1.0f - 0.5f * P - 0.5f * EPSJ * (float)(C - 1) * LOGEPS
                       + 0.5f * EPSJ * T;
        g_pos [w]   = G * S1 + S2;
        g_oodv[w]   = var * mn;
        g_K [br][i] = 0.5f * Sa + HLN2 * sA;
        g_nn[br][i] = nn;
    }
}

// ---------------- kernel 2: gram + weights --------------------------------------
__global__ void __launch_bounds__(128, 4)
gram_kernel(const float* __restrict__ x1, const float* __restrict__ x2,
            const float* __restrict__ l1,  const float* __restrict__ l2) {
    extern __shared__ float sm[];
    float2* sPi = (float2*)sm;            // [C][GTI] (l1,x1)  16 KB
    float2* sPj = sPi + C * GTI;          // [C][GTJ] (l2,x2)  32 KB

    const int tx = threadIdx.x, ty = threadIdx.y;
    const int tid = ty * 16 + tx;
    const int i0 = blockIdx.y * GTI, j0 = blockIdx.x * GTJ;

    {
        int r = tid & 31, c0 = tid >> 5;          // c0: 0..3
        #pragma unroll
        for (int p = 0; p < 4; p++) {
            int cb = c0 + 4 * p;
            float4 lv = *(const float4*)&l1[(i0 + r) * C + cb * 4];
            float4 xv = *(const float4*)&x1[(i0 + r) * C + cb * 4];
            sPi[(cb * 4 + 0) * GTI + r] = make_float2(lv.x, xv.x);
            sPi[(cb * 4 + 1) * GTI + r] = make_float2(lv.y, xv.y);
            sPi[(cb * 4 + 2) * GTI + r] = make_float2(lv.z, xv.z);
            sPi[(cb * 4 + 3) * GTI + r] = make_float2(lv.w, xv.w);
        }
    }
    {
        int r = tid & 63, c0 = tid >> 6;          // c0: 0..1
        #pragma unroll
        for (int p = 0; p < 8; p++) {
            int cb = c0 + 2 * p;
            float4 lv = *(const float4*)&l2[(j0 + r) * C + cb * 4];
            float4 xv = *(const float4*)&x2[(j0 + r) * C + cb * 4];
            sPj[(cb * 4 + 0) * GTJ + r] = make_float2(lv.x, xv.x);
            sPj[(cb * 4 + 1) * GTJ + r] = make_float2(lv.y, xv.y);
            sPj[(cb * 4 + 2) * GTJ + r] = make_float2(lv.z, xv.z);
            sPj[(cb * 4 + 3) * GTJ + r] = make_float2(lv.w, xv.w);
        }
    }
    __syncthreads();

    ull dlx[4][4];
    #pragma unroll
    for (int a = 0; a < 4; a++)
        #pragma unroll
        for (int b = 0; b < 4; b++) dlx[a][b] = 0ull;

    const float4* pi4 = (const float4*)sPi + ty * 2;
    const float4* pj4 = (const float4*)sPj + tx * 2;

    #pragma unroll 4
    for (int c = 0; c < C; c++) {
        F4U pia, pib, pja, pjb;
        pia.f = pi4[c * (GTI / 2)];
        pib.f = pi4[c * (GTI / 2) + 1];
        pja.f = pj4[c * (GTJ / 2)];
        pjb.f = pj4[c * (GTJ / 2) + 1];
        ull pi[4] = {pia.u[0], pia.u[1], pib.u[0], pib.u[1]};
        ull pj[4] = {pja.u[0], pja.u[1], pjb.u[0], pjb.u[1]};
        #pragma unroll
        for (int ki = 0; ki < 4; ki++)
            #pragma unroll
            for (int kj = 0; kj < 4; kj++)
                dlx[ki][kj] = fma2(pi[ki], pj[kj], dlx[ki][kj]);
    }

    F4U nb, na;
    nb.f = *(const float4*)&g_nn[1][j0 + tx * 4];
    na.f = *(const float4*)&g_nn[0][i0 + ty * 4];

    #pragma unroll
    for (int ki = 0; ki < 4; ki++) {
        int i = i0 + ty * 4 + ki;
        F4U wv;
        int rcnt = 0;
        #pragma unroll
        for (int kj = 0; kj < 4; kj++) {
            float2 v = *(float2*)&dlx[ki][kj];           // (dl, dx)
            float d2 = fmaxf(na.s[ki] + nb.s[kj] - 2.0f * v.y, 1e-12f);
            float ed = sqrtf(d2) + 1e-10f;
            float hinge = fmaxf(MARGIN_F - ed, 0.0f);
            float w = hinge * (1.0f - v.x);
            wv.s[kj] = w;
            rcnt += (w > 0.0f) ? 1 : 0;
        }
        *(float4*)&g_w[i][j0 + tx * 4] = wv.f;
        #pragma unroll
        for (int off = 8; off; off >>= 1)
            rcnt += __shfl_down_sync(0xffffffffu, rcnt, off, 16);
        if (tx == 0) atomicAdd(&g_rowcnt[i], rcnt);
    }
}

// ---------------- kernel 3: js log-sums, hybrid MUFU + f32x2 polynomial ---------
// SINGLE 1024-block launch (round 10's two-launch split halved residency and
// serialized two latency-bound half-grids; per-resident-block service rate of
// this hybrid is 1.43x the pure-MUFU version, so at full residency it wins).
// 32i x 32j tile, 128 thr (8tx x 16ty), 2i x 4j micro-tile.
// Per c-iter per ki: kj0,kj1 via packed-f32x2 polynomial log2 (FMA pipe),
// kj2,kj3 via MUFU.LG2 -> pipes overlap.
// Poly: lg2(s) = E + B(f-1.5); E exact via bias trick; B = deg-7 Taylor about
// 1.5 (max err 3.7e-5; validated rel_err 5.9e-6 in round 10).
__global__ void __launch_bounds__(128, 8)
js_kernel(const float* __restrict__ xp1, const float* __restrict__ xp2,
          float* __restrict__ out, int out_size) {
    __shared__ ull  sA2[C * JTI];            // (a,a) duplicated   16 KB
    __shared__ float sB [C * JTJ];           // b                   8 KB

    const int tx = threadIdx.x, ty = threadIdx.y;   // tx 0..7, ty 0..15
    const int tid = ty * 8 + tx;
    const int i0 = blockIdx.y * JTI, j0 = blockIdx.x * JTJ;

    {
        int r = tid & 31, c0 = tid >> 5;             // c0: 0..3
        #pragma unroll
        for (int p = 0; p < 4; p++) {
            int cb = c0 + 4 * p;                     // 0..15
            float4 u = *(const float4*)&xp1[(i0 + r) * C + cb * 4];
            float4 v = *(const float4*)&xp2[(j0 + r) * C + cb * 4];
            sA2[(cb * 4 + 0) * JTI + r] = spl(u.x + EPSJ);
            sA2[(cb * 4 + 1) * JTI + r] = spl(u.y + EPSJ);
            sA2[(cb * 4 + 2) * JTI + r] = spl(u.z + EPSJ);
            sA2[(cb * 4 + 3) * JTI + r] = spl(u.w + EPSJ);
            sB [(cb * 4 + 0) * JTJ + r] = v.x + EPSJ;
            sB [(cb * 4 + 1) * JTJ + r] = v.y + EPSJ;
            sB [(cb * 4 + 2) * JTJ + r] = v.z + EPSJ;
            sB [(cb * 4 + 3) * JTJ + r] = v.w + EPSJ;
        }
    }

    // prefetch pair weights / constants
    F4U w0, w1;
    w0.f = __ldg((const float4*)&g_w[i0 + ty * 2 + 0][j0 + tx * 4]);
    w1.f = __ldg((const float4*)&g_w[i0 + ty * 2 + 1][j0 + tx * 4]);
    float2 Ka = __ldg((const float2*)&g_K[0][i0 + ty * 2]);
    F4U Kb; Kb.f = __ldg((const float4*)&g_K[1][j0 + tx * 4]);

    // poly constants (splatted f32x2); Taylor of log2 about f=1.5
    const ull CB0 = spl( 0.5849625007f);
    const ull CB1 = spl( 0.9617966939f);
    const ull CB2 = spl(-0.3205988980f);
    const ull CB3 = spl( 0.1424883991f);
    const ull CB4 = spl(-0.0712441996f);
    const ull CB5 = spl( 0.0379969064f);
    const ull CB6 = spl(-0.0211094300f);
    const ull CB7 = spl( 0.0120624400f);
    const ull CME = spl(-8388735.0f);        // -(2^23 + 127)
    const ull CMH = spl(-1.5f);

    __syncthreads();

    ull   jp[2];                             // packed jsum (kj0,kj1) per ki
    float jm[2][2];                          // scalar jsum (kj2,kj3) per ki
    jp[0] = jp[1] = 0ull;
    jm[0][0] = jm[0][1] = jm[1][0] = jm[1][1] = 0.0f;

    const ull*   aPtr = sA2 + ty * 2;        // stride JTI per c
    const float4* b4  = (const float4*)sB + tx;   // stride JTJ/4=8 per c

    #pragma unroll 4
    for (int c = 0; c < C; c++) {
        ull aa0 = aPtr[c * JTI];
        ull aa1 = aPtr[c * JTI + 1];
        F4U bv; bv.f = b4[c * (JTJ / 4)];

        #pragma unroll
        for (int ki = 0; ki < 2; ki++) {
            ull aa = ki ? aa1 : aa0;
            // --- poly path: kj0,kj1 packed ---
            U2F s2; s2.u = add2(aa, bv.u[0]);
            unsigned fe0 = (s2.q[0] >> 23) + 0x4B000000u;
            unsigned fe1 = (s2.q[1] >> 23) + 0x4B000000u;
            ull E2 = add2(pk(fe0, fe1), CME);         // exact E = exp-127
            unsigned f0 = (s2.q[0] & 0x007FFFFFu) | 0x3F800000u;
            unsigned f1 = (s2.q[1] & 0x007FFFFFu) | 0x3F800000u;
            ull u2 = add2(pk(f0, f1), CMH);           // f - 1.5 in [-0.5, 0.5)
            ull P = CB7;
            P = fma2(P, u2, CB6);
            P = fma2(P, u2, CB5);
            P = fma2(P, u2, CB4);
            P = fma2(P, u2, CB3);
            P = fma2(P, u2, CB2);
            P = fma2(P, u2, CB1);
            P = fma2(P, u2, CB0);                     // B(u) ~ log2(f)
            ull lg2 = add2(P, E2);
            jp[ki] = fma2(s2.u, lg2, jp[ki]);

            // --- MUFU path: kj2,kj3 scalar ---
            U2F av; av.u = aa;
            float a = av.s[0];
            float sa2 = a + bv.s[2];
            float sa3 = a + bv.s[3];
            jm[ki][0] = fmaf(sa2, __log2f(sa2), jm[ki][0]);
            jm[ki][1] = fmaf(sa3, __log2f(sa3), jm[ki][1]);
        }
    }

    #pragma unroll
    for (int ki = 0; ki < 2; ki++) {
        int i = i0 + ty * 2 + ki;
        float Kai = (ki == 0) ? Ka.x : Ka.y;
        const F4U& wv = (ki == 0) ? w0 : w1;
        U2F jpv; jpv.u = jp[ki];
        float js0 = Kai + Kb.s[0] - HLN2 * jpv.s[0];
        float js1 = Kai + Kb.s[1] - HLN2 * jpv.s[1];
        float js2 = Kai + Kb.s[2] - HLN2 * jm[ki][0];
        float js3 = Kai + Kb.s[3] - HLN2 * jm[ki][1];
        float rsum = wv.s[0] * js0 + wv.s[1] * js1 + wv.s[2] * js2 + wv.s[3] * js3;
        #pragma unroll
        for (int off = 4; off; off >>= 1)
            rsum += __shfl_down_sync(0xffffffffu, rsum, off, 8);
        if (tx == 0) atomicAdd(&g_rowsum[i], rsum);
    }

    // ---- folded finalize: last block to finish reduces everything ----
    __threadfence();
    __syncthreads();
    __shared__ int s_last;
    if (tid == 0) s_last = atomicAdd(&g_done, 1);
    __syncthreads();
    if (s_last != NBLKJ - 1) return;

    float nega = 0.0f, posi = 0.0f, ood = 0.0f;
    for (int r = tid; r < NROWS; r += 128) {
        float rs = __ldcg(&g_rowsum[r]);
        int   rc = __ldcg(&g_rowcnt[r]);
        nega += rs / (float)(rc > 0 ? rc : 1);
    }
    for (int r = tid; r < 2 * NROWS; r += 128) {
        posi += g_pos[r];
        ood  += g_oodv[r];
    }
    float* red = (float*)sA2;
    red[tid]       = nega;
    red[128 + tid] = posi;
    red[256 + tid] = ood;
    __syncthreads();
    for (int off = 64; off; off >>= 1) {
        if (tid < off) {
            red[tid]       += red[tid + off];
            red[128 + tid] += red[128 + tid + off];
            red[256 + tid] += red[256 + tid + off];
        }
        __syncthreads();
    }
    for (int r = 3 + tid; r < out_size; r += 128) out[r] = 0.0f;  // defensive
    if (tid == 0) {
        float ng = red[0];
        float ps = 0.5f * red[128];
        float od = 0.5f * red[256];
        if (out_size > 0) out[0] = ps + ng + 0.5f * od;   // LAM = 0.5
        if (out_size > 1) out[1] = ps;
        if (out_size > 2) out[2] = ng;
    }
}

// ---------------- launch ---------------------------------------------------------
extern "C" void kernel_launch(void* const* d_in, const int* in_sizes, int n_in,
                              void* d_out, int out_size) {
    const float* x1  = (const float*)d_in[0];
    const float* x2  = (const float*)d_in[1];
    const float* xp1 = (const float*)d_in[2];
    const float* xp2 = (const float*)d_in[3];
    const float* l1  = (const float*)d_in[4];
    const float* l2  = (const float*)d_in[5];
    float* out = (float*)d_out;

    row_kernel<<<256, 256>>>(x1, x2, xp1, xp2, l1, l2);

    const int gsmem = C * (GTI + GTJ) * (int)sizeof(float2);   // 49,152 B
    cudaFuncSetAttribute(gram_kernel, cudaFuncAttributeMaxDynamicSharedMemorySize,
                         gsmem);
    gram_kernel<<<dim3(NROWS / GTJ, NROWS / GTI), dim3(16, 8), gsmem>>>(x1, x2, l1, l2);

    // single full-grid js launch: all 1024 blocks resident (8/SM capacity)
    js_kernel<<<dim3(NROWS / JTJ, NROWS / JTI), dim3(8, 16)>>>(xp1, xp2, out, out_size);
}

// round 12
// speedup vs baseline: 1.1282x; 1.0221x over previous
#include <cuda_runtime.h>
#include <math.h>

#define NROWS 1024
#define C 64
#define MARGIN_F 15.0f
#define EPSJ 1e-8f
#define HLN2 0.34657359027997264f   /* 0.5*ln2 */

/* gram kernel tiling */
#define GTI 32
#define GTJ 64
/* js kernel tiling */
#define JTI 32
#define JTJ 32
#define NBLKJ 1024                   /* (1024/JTI)*(1024/JTJ), single launch */

typedef unsigned long long ull;

// ---------------- scratch (static device globals; no allocation) ----------------
__device__ float g_K[2][NROWS];      // 0.5*Sa + 0.5*ln2*sumA  per row
__device__ float g_nn[2][NROWS];     // ||x||^2 per row
__device__ float g_pos[2 * NROWS];   // per-row positive-branch contribution
__device__ float g_oodv[2 * NROWS];  // per-row ood contribution (var*coffi)
__device__ float g_rowsum[NROWS];    // negative-branch per-row pair sums
__device__ int   g_rowcnt[NROWS];    // negative-branch per-row counts
__device__ int   g_done;             // js-kernel completion counter
__device__ float g_w[NROWS][NROWS];  // per-pair weight hinge*(1-dl)  (4 MB)

__device__ __forceinline__ ull fma2(ull a, ull b, ull c) {
    ull d;
    asm("fma.rn.f32x2 %0, %1, %2, %3;" : "=l"(d) : "l"(a), "l"(b), "l"(c));
    return d;
}

union F4U {
    float4 f;
    ull u[2];
    float s[4];
    unsigned q[4];
};

__device__ __forceinline__ float wsum(float v) {
    #pragma unroll
    for (int off = 16; off; off >>= 1) v += __shfl_xor_sync(0xffffffffu, v, off);
    return v;
}
__device__ __forceinline__ float wmin(float v) {
    #pragma unroll
    for (int off = 16; off; off >>= 1)
        v = fminf(v, __shfl_xor_sync(0xffffffffu, v, off));
    return v;
}

// Scalar fast log2 accumulate: acc += s * log2(s), s in [2e-8, 2).
// E exact via float-bias trick (no I2F); mantissa poly = deg-5 Taylor about 1.5
// (|err| <= 3.3e-4 in lg2; measured error scaling from the deg-7 variant
// predicts ~5e-5 total rel_err, 20x inside the 1e-3 budget).
// Cost: SHR+IADD+LOP3 + 3 FADD + 5 FMA + 1 FFMA = 13 fixed-lat ops, no MUFU.
__device__ __forceinline__ float jterm(float s, float acc) {
    int ix = __float_as_int(s);
    float E = __int_as_float((ix >> 23) + 0x4B000000) - 8388735.0f;  // exp-127
    float f = __int_as_float((ix & 0x007FFFFF) | 0x3F800000);        // [1,2)
    float u = f - 1.5f;
    float p =              0.0379969064f;
    p = fmaf(p, u,        -0.0712441996f);
    p = fmaf(p, u,         0.1424883991f);
    p = fmaf(p, u,        -0.3205988980f);
    p = fmaf(p, u,         0.9617966939f);
    p = fmaf(p, u,         0.5849625007f);     // log2(f)
    return fmaf(s, p + E, acc);
}

// ---------------- kernel 1: warp-per-row precompute + positive + ood ------------
__global__ void row_kernel(const float* __restrict__ x1, const float* __restrict__ x2,
                           const float* __restrict__ xp1, const float* __restrict__ xp2,
                           const float* __restrict__ l1,  const float* __restrict__ l2) {
    int gtid = blockIdx.x * blockDim.x + threadIdx.x;
    int w    = gtid >> 5;            // warp id: 0..2047
    int lane = gtid & 31;
    if (gtid == 0) g_done = 0;
    if (gtid < NROWS) { g_rowsum[gtid] = 0.0f; g_rowcnt[gtid] = 0; }

    int br = w >> 10;
    int i  = w & (NROWS - 1);
    const float* xr = (br ? x2  : x1)  + i * C;
    const float* pr = (br ? xp2 : xp1) + i * C;
    const float* lr = (br ? l2  : l1)  + i * C;

    float xv0 = xr[lane], xv1 = xr[lane + 32];
    float A0  = pr[lane] + EPSJ, A1 = pr[lane + 32] + EPSJ;
    float lv0 = lr[lane], lv1 = lr[lane + 32];

    float nn = wsum(fmaf(xv0, xv0, xv1 * xv1));

    float la0 = __logf(A0),                 la1 = __logf(A1);
    float L00 = __logf(0.5f * (A0 + EPSJ)), L01 = __logf(0.5f * (A1 + EPSJ));
    float L10 = __logf(0.5f * (A0 + 1.0f)), L11 = __logf(0.5f * (A1 + 1.0f));
    float P  = fmaf(A0, la0 - L00, A1 * (la1 - L01));
    float T  = L00 + L01;
    float Sa = fmaf(A0, la0, A1 * la1);
    float sA = A0 + A1;

    float pd0 = sqrtf(fmaxf(nn - 2.0f * xv0 + 1.0f, 1e-12f));
    float pd1 = sqrtf(fmaxf(nn - 2.0f * xv1 + 1.0f, 1e-12f));
    float h0  = -0.5f * A0 * (L00 - L10) - 0.5f * EPSJ * L00 + 0.5f * L10;
    float h1  = -0.5f * A1 * (L01 - L11) - 0.5f * EPSJ * L01 + 0.5f * L11;
    float w0  = pd0 * lv0, w1 = pd1 * lv1;
    float S1  = w0 + w1;
    float S2  = fmaf(w0, h0, w1 * h1);
    float r0  = fmaxf(MARGIN_F - pd0, 0.0f) * (1.0f / MARGIN_F);
    float r1  = fmaxf(MARGIN_F - pd1, 0.0f) * (1.0f / MARGIN_F);
    float var = fmaf(r0, r0, r1 * r1);
    float mn  = fminf(1.0f - r0, 1.0f - r1);

    P = wsum(P); T = wsum(T); Sa = wsum(Sa); sA = wsum(sA);
    S1 = wsum(S1); S2 = wsum(S2); var = wsum(var); mn = wmin(mn);

    if (lane == 0) {
        const float LOGEPS = -18.420680743952367f;   // ln(1e-8)
        float G = 1.0f - 0.5f * P - 0.5f * EPSJ * (float)(C - 1) * LOGEPS
                       + 0.5f * EPSJ * T;
        g_pos [w]   = G * S1 + S2;
        g_oodv[w]   = var * mn;
        g_K [br][i] = 0.5f * Sa + HLN2 * sA;
        g_nn[br][i] = nn;
    }
}

// ---------------- kernel 2: gram + weights --------------------------------------
__global__ void __launch_bounds__(128, 4)
gram_kernel(const float* __restrict__ x1, const float* __restrict__ x2,
            const float* __restrict__ l1,  const float* __restrict__ l2) {
    extern __shared__ float sm[];
    float2* sPi = (float2*)sm;            // [C][GTI] (l1,x1)  16 KB
    float2* sPj = sPi + C * GTI;          // [C][GTJ] (l2,x2)  32 KB

    const int tx = threadIdx.x, ty = threadIdx.y;
    const int tid = ty * 16 + tx;
    const int i0 = blockIdx.y * GTI, j0 = blockIdx.x * GTJ;

    {
        int r = tid & 31, c0 = tid >> 5;          // c0: 0..3
        #pragma unroll
        for (int p = 0; p < 4; p++) {
            int cb = c0 + 4 * p;
            float4 lv = *(const float4*)&l1[(i0 + r) * C + cb * 4];
            float4 xv = *(const float4*)&x1[(i0 + r) * C + cb * 4];
            sPi[(cb * 4 + 0) * GTI + r] = make_float2(lv.x, xv.x);
            sPi[(cb * 4 + 1) * GTI + r] = make_float2(lv.y, xv.y);
            sPi[(cb * 4 + 2) * GTI + r] = make_float2(lv.z, xv.z);
            sPi[(cb * 4 + 3) * GTI + r] = make_float2(lv.w, xv.w);
        }
    }
    {
        int r = tid & 63, c0 = tid >> 6;          // c0: 0..1
        #pragma unroll
        for (int p = 0; p < 8; p++) {
            int cb = c0 + 2 * p;
            float4 lv = *(const float4*)&l2[(j0 + r) * C + cb * 4];
            float4 xv = *(const float4*)&x2[(j0 + r) * C + cb * 4];
            sPj[(cb * 4 + 0) * GTJ + r] = make_float2(lv.x, xv.x);
            sPj[(cb * 4 + 1) * GTJ + r] = make_float2(lv.y, xv.y);
            sPj[(cb * 4 + 2) * GTJ + r] = make_float2(lv.z, xv.z);
            sPj[(cb * 4 + 3) * GTJ + r] = make_float2(lv.w, xv.w);
        }
    }
    __syncthreads();

    ull dlx[4][4];
    #pragma unroll
    for (int a = 0; a < 4; a++)
        #pragma unroll
        for (int b = 0; b < 4; b++) dlx[a][b] = 0ull;

    const float4* pi4 = (const float4*)sPi + ty * 2;
    const float4* pj4 = (const float4*)sPj + tx * 2;

    #pragma unroll 4
    for (int c = 0; c < C; c++) {
        F4U pia, pib, pja, pjb;
        pia.f = pi4[c * (GTI / 2)];
        pib.f = pi4[c * (GTI / 2) + 1];
        pja.f = pj4[c * (GTJ / 2)];
        pjb.f = pj4[c * (GTJ / 2) + 1];
        ull pi[4] = {pia.u[0], pia.u[1], pib.u[0], pib.u[1]};
        ull pj[4] = {pja.u[0], pja.u[1], pjb.u[0], pjb.u[1]};
        #pragma unroll
        for (int ki = 0; ki < 4; ki++)
            #pragma unroll
            for (int kj = 0; kj < 4; kj++)
                dlx[ki][kj] = fma2(pi[ki], pj[kj], dlx[ki][kj]);
    }

    F4U nb, na;
    nb.f = *(const float4*)&g_nn[1][j0 + tx * 4];
    na.f = *(const float4*)&g_nn[0][i0 + ty * 4];

    #pragma unroll
    for (int ki = 0; ki < 4; ki++) {
        int i = i0 + ty * 4 + ki;
        F4U wv;
        int rcnt = 0;
        #pragma unroll
        for (int kj = 0; kj < 4; kj++) {
            float2 v = *(float2*)&dlx[ki][kj];           // (dl, dx)
            float d2 = fmaxf(na.s[ki] + nb.s[kj] - 2.0f * v.y, 1e-12f);
            float ed = sqrtf(d2) + 1e-10f;
            float hinge = fmaxf(MARGIN_F - ed, 0.0f);
            float w = hinge * (1.0f - v.x);
            wv.s[kj] = w;
            rcnt += (w > 0.0f) ? 1 : 0;
        }
        *(float4*)&g_w[i][j0 + tx * 4] = wv.f;
        #pragma unroll
        for (int off = 8; off; off >>= 1)
            rcnt += __shfl_down_sync(0xffffffffu, rcnt, off, 16);
        if (tx == 0) atomicAdd(&g_rowcnt[i], rcnt);
    }
}

// ---------------- kernel 3: js log-sums, hybrid MUFU + SCALAR polynomial --------
// Round-11 evidence: packed f32x2 poly is lowered to 2xFFMA + pack/unpack ->
// issue-bound and slower than pure MUFU at equal occupancy. This version keeps
// the validated hybrid pipe-split but implements the poly path with SCALAR
// fixed-lat ops (13/log, deg-5) -> issue ~70 slots/thread/c-iter, MUFU 4.
// Single 1024-block launch, 16 KB smem, <=64 regs -> ~7 blocks/SM, one wave.
// 32i x 32j tile, 128 thr (8tx x 16ty), 2i x 4j micro-tile.
// js = Ka + Kb - 0.5ln2 * sum_c s*lg2(s),  s = A1_ic + A2_jc.
__global__ void __launch_bounds__(128, 8)
js_kernel(const float* __restrict__ xp1, const float* __restrict__ xp2,
          float* __restrict__ out, int out_size) {
    __shared__ float sA[C * JTI];            // a = xp1+eps   8 KB
    __shared__ float sB[C * JTJ];            // b = xp2+eps   8 KB

    const int tx = threadIdx.x, ty = threadIdx.y;   // tx 0..7, ty 0..15
    const int tid = ty * 8 + tx;
    const int i0 = blockIdx.y * JTI, j0 = blockIdx.x * JTJ;

    {
        int r = tid & 31, c0 = tid >> 5;             // c0: 0..3
        #pragma unroll
        for (int p = 0; p < 4; p++) {
            int cb = c0 + 4 * p;                     // 0..15
            float4 u = *(const float4*)&xp1[(i0 + r) * C + cb * 4];
            float4 v = *(const float4*)&xp2[(j0 + r) * C + cb * 4];
            sA[(cb * 4 + 0) * JTI + r] = u.x + EPSJ;
            sA[(cb * 4 + 1) * JTI + r] = u.y + EPSJ;
            sA[(cb * 4 + 2) * JTI + r] = u.z + EPSJ;
            sA[(cb * 4 + 3) * JTI + r] = u.w + EPSJ;
            sB[(cb * 4 + 0) * JTJ + r] = v.x + EPSJ;
            sB[(cb * 4 + 1) * JTJ + r] = v.y + EPSJ;
            sB[(cb * 4 + 2) * JTJ + r] = v.z + EPSJ;
            sB[(cb * 4 + 3) * JTJ + r] = v.w + EPSJ;
        }
    }

    // prefetch pair weights / constants (hidden behind the main loop)
    F4U w0, w1;
    w0.f = __ldg((const float4*)&g_w[i0 + ty * 2 + 0][j0 + tx * 4]);
    w1.f = __ldg((const float4*)&g_w[i0 + ty * 2 + 1][j0 + tx * 4]);
    float2 Ka = __ldg((const float2*)&g_K[0][i0 + ty * 2]);
    F4U Kb; Kb.f = __ldg((const float4*)&g_K[1][j0 + tx * 4]);

    __syncthreads();

    float jsum[2][4];
    #pragma unroll
    for (int a = 0; a < 2; a++)
        #pragma unroll
        for (int b = 0; b < 4; b++) jsum[a][b] = 0.0f;

    const float2* a2 = (const float2*)sA + ty;       // stride JTI/2=16 per c
    const float4* b4 = (const float4*)sB + tx;       // stride JTJ/4=8  per c

    #pragma unroll 4
    for (int c = 0; c < C; c++) {
        float2 av = a2[c * (JTI / 2)];
        F4U bv; bv.f = b4[c * (JTJ / 4)];
        float a[2] = {av.x, av.y};
        #pragma unroll
        for (int ki = 0; ki < 2; ki++) {
            // poly path (FMA/ALU pipes): kj0, kj1
            jsum[ki][0] = jterm(a[ki] + bv.s[0], jsum[ki][0]);
            jsum[ki][1] = jterm(a[ki] + bv.s[1], jsum[ki][1]);
            // MUFU path: kj2, kj3
            float s2 = a[ki] + bv.s[2];
            float s3 = a[ki] + bv.s[3];
            jsum[ki][2] = fmaf(s2, __log2f(s2), jsum[ki][2]);
            jsum[ki][3] = fmaf(s3, __log2f(s3), jsum[ki][3]);
        }
    }

    #pragma unroll
    for (int ki = 0; ki < 2; ki++) {
        int i = i0 + ty * 2 + ki;
        float Kai = (ki == 0) ? Ka.x : Ka.y;
        const F4U& wv = (ki == 0) ? w0 : w1;
        float rsum = 0.0f;
        #pragma unroll
        for (int kj = 0; kj < 4; kj++) {
            float js = Kai + Kb.s[kj] - HLN2 * jsum[ki][kj];
            rsum = fmaf(wv.s[kj], js, rsum);
        }
        #pragma unroll
        for (int off = 4; off; off >>= 1)
            rsum += __shfl_down_sync(0xffffffffu, rsum, off, 8);
        if (tx == 0) atomicAdd(&g_rowsum[i], rsum);
    }

    // ---- folded finalize: last block to finish reduces everything ----
    __threadfence();
    __syncthreads();
    __shared__ int s_last;
    if (tid == 0) s_last = atomicAdd(&g_done, 1);
    __syncthreads();
    if (s_last != NBLKJ - 1) return;

    float nega = 0.0f, posi = 0.0f, ood = 0.0f;
    for (int r = tid; r < NROWS; r += 128) {
        float rs = __ldcg(&g_rowsum[r]);
        int   rc = __ldcg(&g_rowcnt[r]);
        nega += rs / (float)(rc > 0 ? rc : 1);
    }
    for (int r = tid; r < 2 * NROWS; r += 128) {
        posi += g_pos[r];
        ood  += g_oodv[r];
    }
    float* red = sA;                 // reuse smem
    red[tid]       = nega;
    red[128 + tid] = posi;
    red[256 + tid] = ood;
    __syncthreads();
    for (int off = 64; off; off >>= 1) {
        if (tid < off) {
            red[tid]       += red[tid + off];
            red[128 + tid] += red[128 + tid + off];
            red[256 + tid] += red[256 + tid + off];
        }
        __syncthreads();
    }
    for (int r = 3 + tid; r < out_size; r += 128) out[r] = 0.0f;  // defensive
    if (tid == 0) {
        float ng = red[0];
        float ps = 0.5f * red[128];
        float od = 0.5f * red[256];
        if (out_size > 0) out[0] = ps + ng + 0.5f * od;   // LAM = 0.5
        if (out_size > 1) out[1] = ps;
        if (out_size > 2) out[2] = ng;
    }
}

// ---------------- launch ---------------------------------------------------------
extern "C" void kernel_launch(void* const* d_in, const int* in_sizes, int n_in,
                              void* d_out, int out_size) {
    const float* x1  = (const float*)d_in[0];
    const float* x2  = (const float*)d_in[1];
    const float* xp1 = (const float*)d_in[2];
    const float* xp2 = (const float*)d_in[3];
    const float* l1  = (const float*)d_in[4];
    const float* l2  = (const float*)d_in[5];
    float* out = (float*)d_out;

    row_kernel<<<256, 256>>>(x1, x2, xp1, xp2, l1, l2);

    const int gsmem = C * (GTI + GTJ) * (int)sizeof(float2);   // 49,152 B
    cudaFuncSetAttribute(gram_kernel, cudaFuncAttributeMaxDynamicSharedMemorySize,
                         gsmem);
    gram_kernel<<<dim3(NROWS / GTJ, NROWS / GTI), dim3(16, 8), gsmem>>>(x1, x2, l1, l2);

    // single full-grid js launch: all 1024 blocks resident
    js_kernel<<<dim3(NROWS / JTJ, NROWS / JTI), dim3(8, 16)>>>(xp1, xp2, out, out_size);
}

// round 13
// speedup vs baseline: 1.1317x; 1.0031x over previous
#include <cuda_runtime.h>
#include <math.h>

#define NROWS 1024
#define C 64
#define MARGIN_F 15.0f
#define EPSJ 1e-8f
#define HLN2 0.34657359027997264f   /* 0.5*ln2 */

/* gram kernel tiling */
#define GTI 32
#define GTJ 64
/* js kernel tiling */
#define JTI 32
#define JTJ 32
#define NBLKJ 1024                   /* (1024/JTI)*(1024/JTJ), single launch */

typedef unsigned long long ull;

// ---------------- scratch (static device globals; no allocation) ----------------
__device__ float g_K[2][NROWS];      // 0.5*Sa + 0.5*ln2*sumA  per row
__device__ float g_nn[2][NROWS];     // ||x||^2 per row
__device__ float g_pos[2 * NROWS];   // per-row positive-branch contribution
__device__ float g_oodv[2 * NROWS];  // per-row ood contribution (var*coffi)
__device__ float g_rowsum[NROWS];    // negative-branch per-row pair sums
__device__ int   g_rowcnt[NROWS];    // negative-branch per-row counts
__device__ int   g_done;             // js-kernel completion counter
__device__ float g_w[NROWS][NROWS];  // per-pair weight hinge*(1-dl)  (4 MB)

__device__ __forceinline__ ull fma2(ull a, ull b, ull c) {
    ull d;
    asm("fma.rn.f32x2 %0, %1, %2, %3;" : "=l"(d) : "l"(a), "l"(b), "l"(c));
    return d;
}

union F4U {                          // used only in gram kernel (unchanged, works)
    float4 f;
    ull u[2];
    float s[4];
    unsigned q[4];
};

__device__ __forceinline__ float wsum(float v) {
    #pragma unroll
    for (int off = 16; off; off >>= 1) v += __shfl_xor_sync(0xffffffffu, v, off);
    return v;
}
__device__ __forceinline__ float wmin(float v) {
    #pragma unroll
    for (int off = 16; off; off >>= 1)
        v = fminf(v, __shfl_xor_sync(0xffffffffu, v, off));
    return v;
}

// Scalar fast log2 accumulate: acc += s * log2(s), s in (0, ~2).
// E exact via float-bias trick; mantissa poly = deg-4 Chebyshev-downfolded
// Taylor about 1.5 (u5/u6 terms folded into lower degrees; max |err| ~2e-4
// in lg2 -> ~7e-5 total rel_err by measured scaling). 12 issue slots, no MUFU.
__device__ __forceinline__ float jpoly(float s, float acc) {
    int ix = __float_as_int(s);
    float E = __int_as_float((ix >> 23) + 0x4B000000) - 8388735.0f;  // exp-127
    float f = __int_as_float((ix & 0x007FFFFF) | 0x3F800000);        // [1,2)
    float u = f - 1.5f;
    float p =        -0.0791602f;
    p = fmaf(p, u,    0.1543624f);
    p = fmaf(p, u,   -0.3198568f);
    p = fmaf(p, u,    0.9610546f);
    p = fmaf(p, u,    0.5849522f);           // ~log2(f)
    return fmaf(s, p + E, acc);
}

// ---------------- kernel 1: warp-per-row precompute + positive + ood ------------
__global__ void row_kernel(const float* __restrict__ x1, const float* __restrict__ x2,
                           const float* __restrict__ xp1, const float* __restrict__ xp2,
                           const float* __restrict__ l1,  const float* __restrict__ l2) {
    int gtid = blockIdx.x * blockDim.x + threadIdx.x;
    int w    = gtid >> 5;            // warp id: 0..2047
    int lane = gtid & 31;
    if (gtid == 0) g_done = 0;
    if (gtid < NROWS) { g_rowsum[gtid] = 0.0f; g_rowcnt[gtid] = 0; }

    int br = w >> 10;
    int i  = w & (NROWS - 1);
    const float* xr = (br ? x2  : x1)  + i * C;
    const float* pr = (br ? xp2 : xp1) + i * C;
    const float* lr = (br ? l2  : l1)  + i * C;

    float xv0 = xr[lane], xv1 = xr[lane + 32];
    float A0  = pr[lane] + EPSJ, A1 = pr[lane + 32] + EPSJ;
    float lv0 = lr[lane], lv1 = lr[lane + 32];

    float nn = wsum(fmaf(xv0, xv0, xv1 * xv1));

    float la0 = __logf(A0),                 la1 = __logf(A1);
    float L00 = __logf(0.5f * (A0 + EPSJ)), L01 = __logf(0.5f * (A1 + EPSJ));
    float L10 = __logf(0.5f * (A0 + 1.0f)), L11 = __logf(0.5f * (A1 + 1.0f));
    float P  = fmaf(A0, la0 - L00, A1 * (la1 - L01));
    float T  = L00 + L01;
    float Sa = fmaf(A0, la0, A1 * la1);
    float sA = A0 + A1;

    float pd0 = sqrtf(fmaxf(nn - 2.0f * xv0 + 1.0f, 1e-12f));
    float pd1 = sqrtf(fmaxf(nn - 2.0f * xv1 + 1.0f, 1e-12f));
    float h0  = -0.5f * A0 * (L00 - L10) - 0.5f * EPSJ * L00 + 0.5f * L10;
    float h1  = -0.5f * A1 * (L01 - L11) - 0.5f * EPSJ * L01 + 0.5f * L11;
    float w0  = pd0 * lv0, w1 = pd1 * lv1;
    float S1  = w0 + w1;
    float S2  = fmaf(w0, h0, w1 * h1);
    float r0  = fmaxf(MARGIN_F - pd0, 0.0f) * (1.0f / MARGIN_F);
    float r1  = fmaxf(MARGIN_F - pd1, 0.0f) * (1.0f / MARGIN_F);
    float var = fmaf(r0, r0, r1 * r1);
    float mn  = fminf(1.0f - r0, 1.0f - r1);

    P = wsum(P); T = wsum(T); Sa = wsum(Sa); sA = wsum(sA);
    S1 = wsum(S1); S2 = wsum(S2); var = wsum(var); mn = wmin(mn);

    if (lane == 0) {
        const float LOGEPS = -18.420680743952367f;   // ln(1e-8)
        float G = 1.0f - 0.5f * P - 0.5f * EPSJ * (float)(C - 1) * LOGEPS
                       + 0.5f * EPSJ * T;
        g_pos [w]   = G * S1 + S2;
        g_oodv[w]   = var * mn;
        g_K [br][i] = 0.5f * Sa + HLN2 * sA;
        g_nn[br][i] = nn;
    }
}

// ---------------- kernel 2: gram + weights (unchanged, proven) ------------------
__global__ void __launch_bounds__(128, 4)
gram_kernel(const float* __restrict__ x1, const float* __restrict__ x2,
            const float* __restrict__ l1,  const float* __restrict__ l2) {
    extern __shared__ float sm[];
    float2* sPi = (float2*)sm;            // [C][GTI] (l1,x1)  16 KB
    float2* sPj = sPi + C * GTI;          // [C][GTJ] (l2,x2)  32 KB

    const int tx = threadIdx.x, ty = threadIdx.y;
    const int tid = ty * 16 + tx;
    const int i0 = blockIdx.y * GTI, j0 = blockIdx.x * GTJ;

    {
        int r = tid & 31, c0 = tid >> 5;          // c0: 0..3
        #pragma unroll
        for (int p = 0; p < 4; p++) {
            int cb = c0 + 4 * p;
            float4 lv = *(const float4*)&l1[(i0 + r) * C + cb * 4];
            float4 xv = *(const float4*)&x1[(i0 + r) * C + cb * 4];
            sPi[(cb * 4 + 0) * GTI + r] = make_float2(lv.x, xv.x);
            sPi[(cb * 4 + 1) * GTI + r] = make_float2(lv.y, xv.y);
            sPi[(cb * 4 + 2) * GTI + r] = make_float2(lv.z, xv.z);
            sPi[(cb * 4 + 3) * GTI + r] = make_float2(lv.w, xv.w);
        }
    }
    {
        int r = tid & 63, c0 = tid >> 6;          // c0: 0..1
        #pragma unroll
        for (int p = 0; p < 8; p++) {
            int cb = c0 + 2 * p;
            float4 lv = *(const float4*)&l2[(j0 + r) * C + cb * 4];
            float4 xv = *(const float4*)&x2[(j0 + r) * C + cb * 4];
            sPj[(cb * 4 + 0) * GTJ + r] = make_float2(lv.x, xv.x);
            sPj[(cb * 4 + 1) * GTJ + r] = make_float2(lv.y, xv.y);
            sPj[(cb * 4 + 2) * GTJ + r] = make_float2(lv.z, xv.z);
            sPj[(cb * 4 + 3) * GTJ + r] = make_float2(lv.w, xv.w);
        }
    }
    __syncthreads();

    ull dlx[4][4];
    #pragma unroll
    for (int a = 0; a < 4; a++)
        #pragma unroll
        for (int b = 0; b < 4; b++) dlx[a][b] = 0ull;

    const float4* pi4 = (const float4*)sPi + ty * 2;
    const float4* pj4 = (const float4*)sPj + tx * 2;

    #pragma unroll 4
    for (int c = 0; c < C; c++) {
        F4U pia, pib, pja, pjb;
        pia.f = pi4[c * (GTI / 2)];
        pib.f = pi4[c * (GTI / 2) + 1];
        pja.f = pj4[c * (GTJ / 2)];
        pjb.f = pj4[c * (GTJ / 2) + 1];
        ull pi[4] = {pia.u[0], pia.u[1], pib.u[0], pib.u[1]};
        ull pj[4] = {pja.u[0], pja.u[1], pjb.u[0], pjb.u[1]};
        #pragma unroll
        for (int ki = 0; ki < 4; ki++)
            #pragma unroll
            for (int kj = 0; kj < 4; kj++)
                dlx[ki][kj] = fma2(pi[ki], pj[kj], dlx[ki][kj]);
    }

    F4U nb, na;
    nb.f = *(const float4*)&g_nn[1][j0 + tx * 4];
    na.f = *(const float4*)&g_nn[0][i0 + ty * 4];

    #pragma unroll
    for (int ki = 0; ki < 4; ki++) {
        int i = i0 + ty * 4 + ki;
        F4U wv;
        int rcnt = 0;
        #pragma unroll
        for (int kj = 0; kj < 4; kj++) {
            float2 v = *(float2*)&dlx[ki][kj];           // (dl, dx)
            float d2 = fmaxf(na.s[ki] + nb.s[kj] - 2.0f * v.y, 1e-12f);
            float ed = sqrtf(d2) + 1e-10f;
            float hinge = fmaxf(MARGIN_F - ed, 0.0f);
            float w = hinge * (1.0f - v.x);
            wv.s[kj] = w;
            rcnt += (w > 0.0f) ? 1 : 0;
        }
        *(float4*)&g_w[i][j0 + tx * 4] = wv.f;
        #pragma unroll
        for (int off = 8; off; off >>= 1)
            rcnt += __shfl_down_sync(0xffffffffu, rcnt, off, 16);
        if (tx == 0) atomicAdd(&g_rowcnt[i], rcnt);
    }
}

// ---------------- kernel 3: js log-sums, spill-free hybrid (3 MUFU + 5 poly) ----
// Calibration: MUFU.LG2 effective rt ~ 24 cyc/SMSP (round-9 fit). Balance point
// m = 3 MUFU logs + 5 poly logs per 8 pairs -> issue ~511 ~ MUFU ~504 cyc/SMSP
// per c-iter at 7 warps.
// NO unions, NO array-indexed register accesses, launch_bounds(128,7) (<=72
// regs) -> no spills (the round-10/12 regression source).
// 32i x 32j tile, 128 thr (8tx x 16ty), 2i x 4j micro-tile.
__global__ void __launch_bounds__(128, 7)
js_kernel(const float* __restrict__ xp1, const float* __restrict__ xp2,
          float* __restrict__ out, int out_size) {
    __shared__ float sA[C * JTI];            // a = xp1+eps   8 KB
    __shared__ float sB[C * JTJ];            // b = xp2+eps   8 KB

    const int tx = threadIdx.x, ty = threadIdx.y;   // tx 0..7, ty 0..15
    const int tid = ty * 8 + tx;
    const int i0 = blockIdx.y * JTI, j0 = blockIdx.x * JTJ;

    {
        int r = tid & 31, c0 = tid >> 5;             // c0: 0..3
        #pragma unroll
        for (int p = 0; p < 4; p++) {
            int cb = c0 + 4 * p;                     // 0..15
            float4 u = *(const float4*)&xp1[(i0 + r) * C + cb * 4];
            float4 v = *(const float4*)&xp2[(j0 + r) * C + cb * 4];
            sA[(cb * 4 + 0) * JTI + r] = u.x + EPSJ;
            sA[(cb * 4 + 1) * JTI + r] = u.y + EPSJ;
            sA[(cb * 4 + 2) * JTI + r] = u.z + EPSJ;
            sA[(cb * 4 + 3) * JTI + r] = u.w + EPSJ;
            sB[(cb * 4 + 0) * JTJ + r] = v.x + EPSJ;
            sB[(cb * 4 + 1) * JTJ + r] = v.y + EPSJ;
            sB[(cb * 4 + 2) * JTJ + r] = v.z + EPSJ;
            sB[(cb * 4 + 3) * JTJ + r] = v.w + EPSJ;
        }
    }

    // prefetch pair weights / constants (hidden behind the main loop)
    float4 w0 = __ldg((const float4*)&g_w[i0 + ty * 2 + 0][j0 + tx * 4]);
    float4 w1 = __ldg((const float4*)&g_w[i0 + ty * 2 + 1][j0 + tx * 4]);
    float2 Ka = __ldg((const float2*)&g_K[0][i0 + ty * 2]);
    float4 Kb = __ldg((const float4*)&g_K[1][j0 + tx * 4]);

    __syncthreads();

    float j00 = 0.0f, j01 = 0.0f, j02 = 0.0f, j03 = 0.0f;
    float j10 = 0.0f, j11 = 0.0f, j12 = 0.0f, j13 = 0.0f;

    const float2* a2 = (const float2*)sA + ty;       // stride JTI/2=16 per c
    const float4* b4 = (const float4*)sB + tx;       // stride JTJ/4=8  per c

    #pragma unroll 4
    for (int c = 0; c < C; c++) {
        float2 av = a2[c * (JTI / 2)];
        float4 bv = b4[c * (JTJ / 4)];
        // poly path (FMA/ALU pipes): 5 logs
        j00 = jpoly(av.x + bv.x, j00);
        j01 = jpoly(av.x + bv.y, j01);
        j10 = jpoly(av.y + bv.x, j10);
        j11 = jpoly(av.y + bv.y, j11);
        j13 = jpoly(av.y + bv.w, j13);
        // MUFU path: 3 logs
        float s02 = av.x + bv.z;
        float s03 = av.x + bv.w;
        float s12 = av.y + bv.z;
        j02 = fmaf(s02, __log2f(s02), j02);
        j03 = fmaf(s03, __log2f(s03), j03);
        j12 = fmaf(s12, __log2f(s12), j12);
    }

    {   // ki = 0
        int i = i0 + ty * 2;
        float rsum = w0.x * (Ka.x + Kb.x - HLN2 * j00)
                   + w0.y * (Ka.x + Kb.y - HLN2 * j01)
                   + w0.z * (Ka.x + Kb.z - HLN2 * j02)
                   + w0.w * (Ka.x + Kb.w - HLN2 * j03);
        #pragma unroll
        for (int off = 4; off; off >>= 1)
            rsum += __shfl_down_sync(0xffffffffu, rsum, off, 8);
        if (tx == 0) atomicAdd(&g_rowsum[i], rsum);
    }
    {   // ki = 1
        int i = i0 + ty * 2 + 1;
        float rsum = w1.x * (Ka.y + Kb.x - HLN2 * j10)
                   + w1.y * (Ka.y + Kb.y - HLN2 * j11)
                   + w1.z * (Ka.y + Kb.z - HLN2 * j12)
                   + w1.w * (Ka.y + Kb.w - HLN2 * j13);
        #pragma unroll
        for (int off = 4; off; off >>= 1)
            rsum += __shfl_down_sync(0xffffffffu, rsum, off, 8);
        if (tx == 0) atomicAdd(&g_rowsum[i], rsum);
    }

    // ---- folded finalize: last block to finish reduces everything ----
    __threadfence();
    __syncthreads();
    __shared__ int s_last;
    if (tid == 0) s_last = atomicAdd(&g_done, 1);
    __syncthreads();
    if (s_last != NBLKJ - 1) return;

    float nega = 0.0f, posi = 0.0f, ood = 0.0f;
    for (int r = tid; r < NROWS; r += 128) {
        float rs = __ldcg(&g_rowsum[r]);
        int   rc = __ldcg(&g_rowcnt[r]);
        nega += rs / (float)(rc > 0 ? rc : 1);
    }
    for (int r = tid; r < 2 * NROWS; r += 128) {
        posi += g_pos[r];
        ood  += g_oodv[r];
    }
    float* red = sA;                 // reuse smem
    red[tid]       = nega;
    red[128 + tid] = posi;
    red[256 + tid] = ood;
    __syncthreads();
    for (int off = 64; off; off >>= 1) {
        if (tid < off) {
            red[tid]       += red[tid + off];
            red[128 + tid] += red[128 + tid + off];
            red[256 + tid] += red[256 + tid + off];
        }
        __syncthreads();
    }
    for (int r = 3 + tid; r < out_size; r += 128) out[r] = 0.0f;  // defensive
    if (tid == 0) {
        float ng = red[0];
        float ps = 0.5f * red[128];
        float od = 0.5f * red[256];
        if (out_size > 0) out[0] = ps + ng + 0.5f * od;   // LAM = 0.5
        if (out_size > 1) out[1] = ps;
        if (out_size > 2) out[2] = ng;
    }
}

// ---------------- launch ---------------------------------------------------------
extern "C" void kernel_launch(void* const* d_in, const int* in_sizes, int n_in,
                              void* d_out, int out_size) {
    const float* x1  = (const float*)d_in[0];
    const float* x2  = (const float*)d_in[1];
    const float* xp1 = (const float*)d_in[2];
    const float* xp2 = (const float*)d_in[3];
    const float* l1  = (const float*)d_in[4];
    const float* l2  = (const float*)d_in[5];
    float* out = (float*)d_out;

    row_kernel<<<256, 256>>>(x1, x2, xp1, xp2, l1, l2);

    const int gsmem = C * (GTI + GTJ) * (int)sizeof(float2);   // 49,152 B
    cudaFuncSetAttribute(gram_kernel, cudaFuncAttributeMaxDynamicSharedMemorySize,
                         gsmem);
    gram_kernel<<<dim3(NROWS / GTJ, NROWS / GTI), dim3(16, 8), gsmem>>>(x1, x2, l1, l2);

    // single full-grid js launch: all 1024 blocks resident (7/SM capacity)
    js_kernel<<<dim3(NROWS / JTJ, NROWS / JTI), dim3(8, 16)>>>(xp1, xp2, out, out_size);
}

// round 14
// speedup vs baseline: 1.2125x; 1.0714x over previous
#include <cuda_runtime.h>
#include <math.h>

#define NROWS 1024
#define C 64
#define MARGIN_F 15.0f
#define EPSJ 1e-8f
#define HLN2 0.34657359027997264f   /* 0.5*ln2 */

/* gram kernel tiling */
#define GTI 32
#define GTJ 64
/* js kernel tiling: 32i x 16j -> 2048 blocks -> ~13.8 blocks/SM residency */
#define JTI 32
#define JTJ 16
#define NBLKJ 2048                   /* (1024/JTI)*(1024/JTJ), single launch */

typedef unsigned long long ull;

// ---------------- scratch (static device globals; no allocation) ----------------
__device__ float g_K[2][NROWS];      // 0.5*Sa + 0.5*ln2*sumA  per row
__device__ float g_nn[2][NROWS];     // ||x||^2 per row
__device__ float g_pos[2 * NROWS];   // per-row positive-branch contribution
__device__ float g_oodv[2 * NROWS];  // per-row ood contribution (var*coffi)
__device__ float g_rowsum[NROWS];    // negative-branch per-row pair sums
__device__ int   g_rowcnt[NROWS];    // negative-branch per-row counts
__device__ int   g_done;             // js-kernel completion counter
__device__ float g_w[NROWS][NROWS];  // per-pair weight hinge*(1-dl)  (4 MB)

__device__ __forceinline__ ull fma2(ull a, ull b, ull c) {
    ull d;
    asm("fma.rn.f32x2 %0, %1, %2, %3;" : "=l"(d) : "l"(a), "l"(b), "l"(c));
    return d;
}

union F4U {                          // used only in gram kernel (proven)
    float4 f;
    ull u[2];
    float s[4];
    unsigned q[4];
};

__device__ __forceinline__ float wsum(float v) {
    #pragma unroll
    for (int off = 16; off; off >>= 1) v += __shfl_xor_sync(0xffffffffu, v, off);
    return v;
}
__device__ __forceinline__ float wmin(float v) {
    #pragma unroll
    for (int off = 16; off; off >>= 1)
        v = fminf(v, __shfl_xor_sync(0xffffffffu, v, off));
    return v;
}

// ---------------- kernel 1: warp-per-row precompute + positive + ood ------------
__global__ void row_kernel(const float* __restrict__ x1, const float* __restrict__ x2,
                           const float* __restrict__ xp1, const float* __restrict__ xp2,
                           const float* __restrict__ l1,  const float* __restrict__ l2) {
    int gtid = blockIdx.x * blockDim.x + threadIdx.x;
    int w    = gtid >> 5;            // warp id: 0..2047
    int lane = gtid & 31;
    if (gtid == 0) g_done = 0;
    if (gtid < NROWS) { g_rowsum[gtid] = 0.0f; g_rowcnt[gtid] = 0; }

    int br = w >> 10;
    int i  = w & (NROWS - 1);
    const float* xr = (br ? x2  : x1)  + i * C;
    const float* pr = (br ? xp2 : xp1) + i * C;
    const float* lr = (br ? l2  : l1)  + i * C;

    float xv0 = xr[lane], xv1 = xr[lane + 32];
    float A0  = pr[lane] + EPSJ, A1 = pr[lane + 32] + EPSJ;
    float lv0 = lr[lane], lv1 = lr[lane + 32];

    float nn = wsum(fmaf(xv0, xv0, xv1 * xv1));

    float la0 = __logf(A0),                 la1 = __logf(A1);
    float L00 = __logf(0.5f * (A0 + EPSJ)), L01 = __logf(0.5f * (A1 + EPSJ));
    float L10 = __logf(0.5f * (A0 + 1.0f)), L11 = __logf(0.5f * (A1 + 1.0f));
    float P  = fmaf(A0, la0 - L00, A1 * (la1 - L01));
    float T  = L00 + L01;
    float Sa = fmaf(A0, la0, A1 * la1);
    float sA = A0 + A1;

    float pd0 = sqrtf(fmaxf(nn - 2.0f * xv0 + 1.0f, 1e-12f));
    float pd1 = sqrtf(fmaxf(nn - 2.0f * xv1 + 1.0f, 1e-12f));
    float h0  = -0.5f * A0 * (L00 - L10) - 0.5f * EPSJ * L00 + 0.5f * L10;
    float h1  = -0.5f * A1 * (L01 - L11) - 0.5f * EPSJ * L01 + 0.5f * L11;
    float w0  = pd0 * lv0, w1 = pd1 * lv1;
    float S1  = w0 + w1;
    float S2  = fmaf(w0, h0, w1 * h1);
    float r0  = fmaxf(MARGIN_F - pd0, 0.0f) * (1.0f / MARGIN_F);
    float r1  = fmaxf(MARGIN_F - pd1, 0.0f) * (1.0f / MARGIN_F);
    float var = fmaf(r0, r0, r1 * r1);
    float mn  = fminf(1.0f - r0, 1.0f - r1);

    P = wsum(P); T = wsum(T); Sa = wsum(Sa); sA = wsum(sA);
    S1 = wsum(S1); S2 = wsum(S2); var = wsum(var); mn = wmin(mn);

    if (lane == 0) {
        const float LOGEPS = -18.420680743952367f;   // ln(1e-8)
        float G = 1.0f - 0.5f * P - 0.5f * EPSJ * (float)(C - 1) * LOGEPS
                       + 0.5f * EPSJ * T;
        g_pos [w]   = G * S1 + S2;
        g_oodv[w]   = var * mn;
        g_K [br][i] = 0.5f * Sa + HLN2 * sA;
        g_nn[br][i] = nn;
    }
}

// ---------------- kernel 2: gram + weights (unchanged, proven) ------------------
__global__ void __launch_bounds__(128, 4)
gram_kernel(const float* __restrict__ x1, const float* __restrict__ x2,
            const float* __restrict__ l1,  const float* __restrict__ l2) {
    extern __shared__ float sm[];
    float2* sPi = (float2*)sm;            // [C][GTI] (l1,x1)  16 KB
    float2* sPj = sPi + C * GTI;          // [C][GTJ] (l2,x2)  32 KB

    const int tx = threadIdx.x, ty = threadIdx.y;
    const int tid = ty * 16 + tx;
    const int i0 = blockIdx.y * GTI, j0 = blockIdx.x * GTJ;

    {
        int r = tid & 31, c0 = tid >> 5;          // c0: 0..3
        #pragma unroll
        for (int p = 0; p < 4; p++) {
            int cb = c0 + 4 * p;
            float4 lv = *(const float4*)&l1[(i0 + r) * C + cb * 4];
            float4 xv = *(const float4*)&x1[(i0 + r) * C + cb * 4];
            sPi[(cb * 4 + 0) * GTI + r] = make_float2(lv.x, xv.x);
            sPi[(cb * 4 + 1) * GTI + r] = make_float2(lv.y, xv.y);
            sPi[(cb * 4 + 2) * GTI + r] = make_float2(lv.z, xv.z);
            sPi[(cb * 4 + 3) * GTI + r] = make_float2(lv.w, xv.w);
        }
    }
    {
        int r = tid & 63, c0 = tid >> 6;          // c0: 0..1
        #pragma unroll
        for (int p = 0; p < 8; p++) {
            int cb = c0 + 2 * p;
            float4 lv = *(const float4*)&l2[(j0 + r) * C + cb * 4];
            float4 xv = *(const float4*)&x2[(j0 + r) * C + cb * 4];
            sPj[(cb * 4 + 0) * GTJ + r] = make_float2(lv.x, xv.x);
            sPj[(cb * 4 + 1) * GTJ + r] = make_float2(lv.y, xv.y);
            sPj[(cb * 4 + 2) * GTJ + r] = make_float2(lv.z, xv.z);
            sPj[(cb * 4 + 3) * GTJ + r] = make_float2(lv.w, xv.w);
        }
    }
    __syncthreads();

    ull dlx[4][4];
    #pragma unroll
    for (int a = 0; a < 4; a++)
        #pragma unroll
        for (int b = 0; b < 4; b++) dlx[a][b] = 0ull;

    const float4* pi4 = (const float4*)sPi + ty * 2;
    const float4* pj4 = (const float4*)sPj + tx * 2;

    #pragma unroll 4
    for (int c = 0; c < C; c++) {
        F4U pia, pib, pja, pjb;
        pia.f = pi4[c * (GTI / 2)];
        pib.f = pi4[c * (GTI / 2) + 1];
        pja.f = pj4[c * (GTJ / 2)];
        pjb.f = pj4[c * (GTJ / 2) + 1];
        ull pi[4] = {pia.u[0], pia.u[1], pib.u[0], pib.u[1]};
        ull pj[4] = {pja.u[0], pja.u[1], pjb.u[0], pjb.u[1]};
        #pragma unroll
        for (int ki = 0; ki < 4; ki++)
            #pragma unroll
            for (int kj = 0; kj < 4; kj++)
                dlx[ki][kj] = fma2(pi[ki], pj[kj], dlx[ki][kj]);
    }

    F4U nb, na;
    nb.f = *(const float4*)&g_nn[1][j0 + tx * 4];
    na.f = *(const float4*)&g_nn[0][i0 + ty * 4];

    #pragma unroll
    for (int ki = 0; ki < 4; ki++) {
        int i = i0 + ty * 4 + ki;
        F4U wv;
        int rcnt = 0;
        #pragma unroll
        for (int kj = 0; kj < 4; kj++) {
            float2 v = *(float2*)&dlx[ki][kj];           // (dl, dx)
            float d2 = fmaxf(na.s[ki] + nb.s[kj] - 2.0f * v.y, 1e-12f);
            float ed = sqrtf(d2) + 1e-10f;
            float hinge = fmaxf(MARGIN_F - ed, 0.0f);
            float w = hinge * (1.0f - v.x);
            wv.s[kj] = w;
            rcnt += (w > 0.0f) ? 1 : 0;
        }
        *(float4*)&g_w[i][j0 + tx * 4] = wv.f;
        #pragma unroll
        for (int off = 8; off; off >>= 1)
            rcnt += __shfl_down_sync(0xffffffffu, rcnt, off, 16);
        if (tx == 0) atomicAdd(&g_rowcnt[i], rcnt);
    }
}

// ---------------- kernel 3: js log-sums, PURE MUFU at DOUBLE occupancy ----------
// Every previous js variant was capped at 6.9 blocks/SM by the 1024-block grid
// itself (latency-starved MUFU, eff rt ~21 vs spec 8). This version: 32i x 16j
// tiles -> 2048 blocks -> 13.8 blocks/SM all-resident (12 KB smem, ~25 regs,
// launch_bounds(128,14)) = 13.8 warps/SMSP. Pure MUFU inner loop (3 slots/log),
// 2i x 2j micro-tile, W/K loads AFTER the loop (no prefetch registers).
__global__ void __launch_bounds__(128, 14)
js_kernel(const float* __restrict__ xp1, const float* __restrict__ xp2,
          float* __restrict__ out, int out_size) {
    __shared__ float sA[C * JTI];            // a = xp1+eps   8 KB
    __shared__ float sB[C * JTJ];            // b = xp2+eps   4 KB
    __shared__ int s_last;

    const int tx = threadIdx.x, ty = threadIdx.y;   // tx 0..7, ty 0..15
    const int tid = ty * 8 + tx;
    const int i0 = blockIdx.y * JTI, j0 = blockIdx.x * JTJ;

    {
        int r = tid & 31, c0 = tid >> 5;             // c0: 0..3
        #pragma unroll
        for (int p = 0; p < 4; p++) {
            int cb = c0 + 4 * p;                     // 0..15
            float4 u = *(const float4*)&xp1[(i0 + r) * C + cb * 4];
            sA[(cb * 4 + 0) * JTI + r] = u.x + EPSJ;
            sA[(cb * 4 + 1) * JTI + r] = u.y + EPSJ;
            sA[(cb * 4 + 2) * JTI + r] = u.z + EPSJ;
            sA[(cb * 4 + 3) * JTI + r] = u.w + EPSJ;
        }
    }
    {
        int r = tid & 15, c0 = tid >> 4;             // c0: 0..7
        #pragma unroll
        for (int p = 0; p < 2; p++) {
            int cb = c0 + 8 * p;                     // 0..15
            float4 v = *(const float4*)&xp2[(j0 + r) * C + cb * 4];
            sB[(cb * 4 + 0) * JTJ + r] = v.x + EPSJ;
            sB[(cb * 4 + 1) * JTJ + r] = v.y + EPSJ;
            sB[(cb * 4 + 2) * JTJ + r] = v.z + EPSJ;
            sB[(cb * 4 + 3) * JTJ + r] = v.w + EPSJ;
        }
    }
    __syncthreads();

    float j00 = 0.0f, j01 = 0.0f, j10 = 0.0f, j11 = 0.0f;

    const float2* a2 = (const float2*)sA + ty;       // stride JTI/2=16 per c
    const float2* b2 = (const float2*)sB + tx;       // stride JTJ/2=8  per c

    #pragma unroll 8
    for (int c = 0; c < C; c++) {
        float2 av = a2[c * (JTI / 2)];
        float2 bv = b2[c * (JTJ / 2)];
        float s00 = av.x + bv.x;
        float s01 = av.x + bv.y;
        float s10 = av.y + bv.x;
        float s11 = av.y + bv.y;
        j00 = fmaf(s00, __log2f(s00), j00);
        j01 = fmaf(s01, __log2f(s01), j01);
        j10 = fmaf(s10, __log2f(s10), j10);
        j11 = fmaf(s11, __log2f(s11), j11);
    }

    // W/K loads after the loop (L2-resident; once per block)
    {
        int i = i0 + ty * 2;
        float2 w0 = *(const float2*)&g_w[i + 0][j0 + tx * 2];
        float2 w1 = *(const float2*)&g_w[i + 1][j0 + tx * 2];
        float2 Ka = *(const float2*)&g_K[0][i];
        float2 Kb = *(const float2*)&g_K[1][j0 + tx * 2];

        float rsum0 = w0.x * (Ka.x + Kb.x - HLN2 * j00)
                    + w0.y * (Ka.x + Kb.y - HLN2 * j01);
        float rsum1 = w1.x * (Ka.y + Kb.x - HLN2 * j10)
                    + w1.y * (Ka.y + Kb.y - HLN2 * j11);
        #pragma unroll
        for (int off = 4; off; off >>= 1) {
            rsum0 += __shfl_down_sync(0xffffffffu, rsum0, off, 8);
            rsum1 += __shfl_down_sync(0xffffffffu, rsum1, off, 8);
        }
        if (tx == 0) {
            atomicAdd(&g_rowsum[i + 0], rsum0);
            atomicAdd(&g_rowsum[i + 1], rsum1);
        }
    }

    // ---- folded finalize: last block to finish reduces everything ----
    __threadfence();
    __syncthreads();
    if (tid == 0) s_last = atomicAdd(&g_done, 1);
    __syncthreads();
    if (s_last != NBLKJ - 1) return;

    float nega = 0.0f, posi = 0.0f, ood = 0.0f;
    for (int r = tid; r < NROWS; r += 128) {
        float rs = __ldcg(&g_rowsum[r]);
        int   rc = __ldcg(&g_rowcnt[r]);
        nega += rs / (float)(rc > 0 ? rc : 1);
    }
    for (int r = tid; r < 2 * NROWS; r += 128) {
        posi += g_pos[r];
        ood  += g_oodv[r];
    }
    float* red = sA;                 // reuse smem
    red[tid]       = nega;
    red[128 + tid] = posi;
    red[256 + tid] = ood;
    __syncthreads();
    for (int off = 64; off; off >>= 1) {
        if (tid < off) {
            red[tid]       += red[tid + off];
            red[128 + tid] += red[128 + tid + off];
            red[256 + tid] += red[256 + tid + off];
        }
        __syncthreads();
    }
    for (int r = 3 + tid; r < out_size; r += 128) out[r] = 0.0f;  // defensive
    if (tid == 0) {
        float ng = red[0];
        float ps = 0.5f * red[128];
        float od = 0.5f * red[256];
        if (out_size > 0) out[0] = ps + ng + 0.5f * od;   // LAM = 0.5
        if (out_size > 1) out[1] = ps;
        if (out_size > 2) out[2] = ng;
    }
}

// ---------------- launch ---------------------------------------------------------
extern "C" void kernel_launch(void* const* d_in, const int* in_sizes, int n_in,
                              void* d_out, int out_size) {
    const float* x1  = (const float*)d_in[0];
    const float* x2  = (const float*)d_in[1];
    const float* xp1 = (const float*)d_in[2];
    const float* xp2 = (const float*)d_in[3];
    const float* l1  = (const float*)d_in[4];
    const float* l2  = (const float*)d_in[5];
    float* out = (float*)d_out;

    row_kernel<<<256, 256>>>(x1, x2, xp1, xp2, l1, l2);

    const int gsmem = C * (GTI + GTJ) * (int)sizeof(float2);   // 49,152 B
    cudaFuncSetAttribute(gram_kernel, cudaFuncAttributeMaxDynamicSharedMemorySize,
                         gsmem);
    gram_kernel<<<dim3(NROWS / GTJ, NROWS / GTI), dim3(16, 8), gsmem>>>(x1, x2, l1, l2);

    // single full-grid js launch: 2048 blocks, ~13.8/SM all-resident
    js_kernel<<<dim3(NROWS / JTJ, NROWS / JTI), dim3(8, 16)>>>(xp1, xp2, out, out_size);
}